// round 11
// baseline (speedup 1.0000x reference)
#include <cuda_runtime.h>
#include <math.h>

#define N_NODES 100000
#define N_EDGES 1600000
#define IN_F    128
#define HF      64
#define OUTF    40
#define EPSB    1e-5f

#define G1BLK   296     // gemm1 blocks inside each fat kernel
#define AUXBLK  1184    // edge-work blocks inside each fat kernel
#define N_TILES 6250    // 100000 / 16
#define TILE_SPLIT 3000 // gemm1 tiles done in fatA; rest in fatB

// ---------------- f32x2 packed-FMA helpers ------------------------------------
union F4U { float4 f; unsigned long long u[2]; };

__device__ __forceinline__ unsigned long long ffma2(unsigned long long a,
                                                    unsigned long long b,
                                                    unsigned long long c) {
    unsigned long long d;
    asm("fma.rn.f32x2 %0, %1, %2, %3;" : "=l"(d) : "l"(a), "l"(b), "l"(c));
    return d;
}

__device__ __forceinline__ float2 u2f(unsigned long long v) {
    float2 f;
    asm("mov.b64 {%0, %1}, %2;" : "=f"(f.x), "=f"(f.y) : "l"(v));
    return f;
}

// ---------------- scratch (device globals; no allocation) ---------------------
__device__ __align__(16) float g_h  [N_NODES * HF];   // h1, then h2
__device__ __align__(16) float g_a  [N_NODES * HF];   // x1_pre -> x1
__device__ __align__(16) float g_a2 [N_NODES * HF];   // x2
__device__ float g_dinv[N_NODES];
__device__ int   g_deg [N_NODES];
__device__ int   g_rowloc[N_NODES];
__device__ int   g_rowstart[N_NODES + 1];
__device__ int   g_cursor[N_NODES];
__device__ int   g_btot[128];
__device__ int   g_boff[128];
__device__ int   g_src32[N_EDGES];
__device__ int   g_dst32[N_EDGES];
__device__ __align__(8) int2 g_edge[N_EDGES];        // {src, norm as float bits}
__device__ float g_sum [HF];
__device__ float g_sumsq[HF];
__device__ int   g_is64;

// ---------------- zero + dtype autodetect ------------------------------------
__global__ void k_zero_detect(const int* ei32) {
    int i = blockIdx.x * blockDim.x + threadIdx.x;
    if (i < N_NODES) g_deg[i] = 0;
    if (i < HF) { g_sum[i] = 0.f; g_sumsq[i] = 0.f; }
    if (i == 0) {
        int all0 = 1;
        for (int t = 0; t < 64; t++)
            if (ei32[2 * t + 1] != 0) { all0 = 0; break; }
        g_is64 = all0;
    }
}

// ---------------- GEMM1 body: g_h = x0 @ W1, 256 thr, 16-row tiles -------------
__device__ __forceinline__ void gemm1_body(const float* __restrict__ x0,
                                           const float* __restrict__ W1,
                                           int bid, int nb, int t0, int t1) {
    __shared__ __align__(16) float Wt[HF * 132];
    __shared__ __align__(16) float4 xs[16 * 32];   // [16 rows][128]
    int tid = threadIdx.x;
    for (int i = tid; i < IN_F * HF; i += 256) {
        int k = i >> 6, c = i & 63;
        Wt[c * 132 + k] = W1[i];
    }
    __syncthreads();
    int w = tid >> 5, lane = tid & 31;
    int c = (w & 1) * 32 + lane;
    int rg = (w >> 1) * 4;                          // 4 row-groups of 4 rows
    const float4* wv = (const float4*)(Wt + c * 132);
    for (int tile = t0 + bid; tile < t1; tile += nb) {
        int row0 = tile * 16;
        __syncthreads();
        for (int i = tid; i < 16 * 32; i += 256) {
            int r = i >> 5, c4 = i & 31;
            xs[i] = ((const float4*)(x0 + (size_t)(row0 + r) * IN_F))[c4];
        }
        __syncthreads();
        unsigned long long al[4] = {0, 0, 0, 0};
        unsigned long long ah[4] = {0, 0, 0, 0};
#pragma unroll 4
        for (int k4 = 0; k4 < 32; k4++) {
            F4U wq; wq.f = wv[k4];
#pragma unroll
            for (int r = 0; r < 4; r++) {
                F4U xq; xq.f = xs[(rg + r) * 32 + k4];
                al[r] = ffma2(wq.u[0], xq.u[0], al[r]);
                ah[r] = ffma2(wq.u[1], xq.u[1], ah[r]);
            }
        }
#pragma unroll
        for (int r = 0; r < 4; r++) {
            float2 a = u2f(al[r]), b = u2f(ah[r]);
            g_h[(size_t)(row0 + rg + r) * HF + c] = (a.x + a.y) + (b.x + b.y);
        }
    }
}

// ---------------- deg/cvt body (grid-stride) -----------------------------------
__device__ __forceinline__ void deg_body(const void* ei, int bid, int nb) {
    int stride = nb * 256;
    for (int e = bid * 256 + (int)threadIdx.x; e < N_EDGES; e += stride) {
        int s, d;
        if (g_is64) {
            const long long* p = (const long long*)ei;
            s = (int)p[e];
            d = (int)p[N_EDGES + e];
        } else {
            const int* p = (const int*)ei;
            s = p[e];
            d = p[N_EDGES + e];
        }
        g_src32[e] = s;
        g_dst32[e] = d;
        atomicAdd(&g_deg[d], 1);
    }
}

// ---------------- bucket body (grid-stride): CSR fill, ST.64 payload -----------
__device__ __forceinline__ void bucket_body(int bid, int nb) {
    int stride = nb * 256;
    for (int e = bid * 256 + (int)threadIdx.x; e < N_EDGES; e += stride) {
        int s = g_src32[e];
        int d = g_dst32[e];
        int pos = atomicAdd(&g_cursor[d], 1);
        int2 pay;
        pay.x = s;
        pay.y = __float_as_int(g_dinv[s] * g_dinv[d]);
        g_edge[pos] = pay;
    }
}

// ---------------- fat kernels: overlap gemm1 with CSR build --------------------
__global__ void k_fatA(const float* __restrict__ x0, const float* __restrict__ W1,
                       const void* ei) {
    if (blockIdx.x < G1BLK) gemm1_body(x0, W1, blockIdx.x, G1BLK, 0, TILE_SPLIT);
    else                    deg_body(ei, blockIdx.x - G1BLK, AUXBLK);
}

__global__ void k_fatB(const float* __restrict__ x0, const float* __restrict__ W1) {
    if (blockIdx.x < G1BLK) gemm1_body(x0, W1, blockIdx.x, G1BLK, TILE_SPLIT, N_TILES);
    else                    bucket_body(blockIdx.x - G1BLK, AUXBLK);
}

// ---------------- 3-phase exclusive scan over degrees (known-good) -------------
__global__ void k_scanA() {
    __shared__ int sh[1024];
    int t = threadIdx.x;
    int i = blockIdx.x * 1024 + t;
    int v = (i < N_NODES) ? g_deg[i] : 0;
    sh[t] = v;
    __syncthreads();
    for (int off = 1; off < 1024; off <<= 1) {
        int x = (t >= off) ? sh[t - off] : 0;
        __syncthreads();
        sh[t] += x;
        __syncthreads();
    }
    if (i < N_NODES) g_rowloc[i] = sh[t] - v;
    if (t == 1023) g_btot[blockIdx.x] = sh[t];
}

__global__ void k_scanB() {
    __shared__ int sh[128];
    int t = threadIdx.x;
    int v = (t < 98) ? g_btot[t] : 0;
    sh[t] = v;
    __syncthreads();
    for (int off = 1; off < 128; off <<= 1) {
        int x = (t >= off) ? sh[t - off] : 0;
        __syncthreads();
        sh[t] += x;
        __syncthreads();
    }
    if (t < 98) g_boff[t] = sh[t] - v;
}

__global__ void k_scanC() {
    int i = blockIdx.x * blockDim.x + threadIdx.x;
    if (i < N_NODES) {
        int base = g_rowloc[i] + g_boff[i >> 10];
        g_rowstart[i] = base;
        g_cursor[i] = base;
        g_dinv[i] = rsqrtf((float)g_deg[i] + 1.0f);
    }
    if (i == 0) g_rowstart[N_NODES] = N_EDGES;
}

// ---------------- aggregation (+fused BN stats on layer 0) --------------------
__global__ void k_agg(int layer, const float* __restrict__ bias) {
    const float* h = g_h;
    float* out = (layer == 0) ? g_a : g_a2;
    int w = threadIdx.x >> 5;
    int n = blockIdx.x * 8 + w;
    int lane = threadIdx.x & 31;
    int rs = g_rowstart[n];
    int re = g_rowstart[n + 1];
    float ax = 0.f, ay = 0.f;

    for (int j0 = rs; j0 < re; j0 += 32) {
        int idx = j0 + lane;
        int s = 0; float nrm = 0.f;
        if (idx < re) {
            int2 pay = g_edge[idx];
            s = pay.x;
            nrm = __int_as_float(pay.y);
        }
        int cnt = min(32, re - j0);
        int t = 0;
        for (; t + 4 <= cnt; t += 4) {
            int s0 = __shfl_sync(0xffffffffu, s, t);
            int s1 = __shfl_sync(0xffffffffu, s, t + 1);
            int s2 = __shfl_sync(0xffffffffu, s, t + 2);
            int s3 = __shfl_sync(0xffffffffu, s, t + 3);
            float n0 = __shfl_sync(0xffffffffu, nrm, t);
            float n1 = __shfl_sync(0xffffffffu, nrm, t + 1);
            float n2 = __shfl_sync(0xffffffffu, nrm, t + 2);
            float n3 = __shfl_sync(0xffffffffu, nrm, t + 3);
            float2 v0 = *(const float2*)(h + (size_t)s0 * HF + lane * 2);
            float2 v1 = *(const float2*)(h + (size_t)s1 * HF + lane * 2);
            float2 v2 = *(const float2*)(h + (size_t)s2 * HF + lane * 2);
            float2 v3 = *(const float2*)(h + (size_t)s3 * HF + lane * 2);
            ax = fmaf(v0.x, n0, ax); ay = fmaf(v0.y, n0, ay);
            ax = fmaf(v1.x, n1, ax); ay = fmaf(v1.y, n1, ay);
            ax = fmaf(v2.x, n2, ax); ay = fmaf(v2.y, n2, ay);
            ax = fmaf(v3.x, n3, ax); ay = fmaf(v3.y, n3, ay);
        }
        for (; t < cnt; t++) {
            int st = __shfl_sync(0xffffffffu, s, t);
            float nt = __shfl_sync(0xffffffffu, nrm, t);
            float2 v = *(const float2*)(h + (size_t)st * HF + lane * 2);
            ax = fmaf(v.x, nt, ax); ay = fmaf(v.y, nt, ay);
        }
    }
    float di = g_dinv[n];
    float d2 = di * di;
    float2 hv = *(const float2*)(h + (size_t)n * HF + lane * 2);
    float2 bv = *(const float2*)(bias + lane * 2);
    float2 o;
    o.x = ax + hv.x * d2 + bv.x;
    o.y = ay + hv.y * d2 + bv.y;
    *(float2*)(out + (size_t)n * HF + lane * 2) = o;

    if (layer == 0) {
        __shared__ float ssum[8][66], ssq[8][66];
        ssum[w][2 * lane]     = o.x;
        ssum[w][2 * lane + 1] = o.y;
        ssq [w][2 * lane]     = o.x * o.x;
        ssq [w][2 * lane + 1] = o.y * o.y;
        __syncthreads();
        if (threadIdx.x < 64) {
            float a = 0.f, b = 0.f;
#pragma unroll
            for (int j = 0; j < 8; j++) { a += ssum[j][threadIdx.x]; b += ssq[j][threadIdx.x]; }
            atomicAdd(&g_sum[threadIdx.x], a);
            atomicAdd(&g_sumsq[threadIdx.x], b);
        }
    }
}

// ---------------- GEMM2: BN+relu(g_a) -> x1 (to g_a); h2 = x1 @ W2 -> g_h ------
__global__ void k_gemm2(const float* __restrict__ W2,
                        const float* __restrict__ g1, const float* __restrict__ be1) {
    __shared__ __align__(16) float Wt[HF * 68];
    __shared__ __align__(16) float4 xs[16 * 16];   // [16 rows][64]
    __shared__ __align__(16) float s_sc[HF], s_sf[HF];

    int tid = threadIdx.x;
    for (int i = tid; i < HF * HF; i += 128) {
        int k = i >> 6, c = i & 63;
        Wt[c * 68 + k] = W2[i];
    }
    if (tid < HF) {
        float mu  = g_sum[tid] * (1.0f / N_NODES);
        float var = g_sumsq[tid] * (1.0f / N_NODES) - mu * mu;
        float sc  = rsqrtf(var + EPSB) * g1[tid];
        s_sc[tid] = sc;
        s_sf[tid] = be1[tid] - mu * sc;
    }
    __syncthreads();

    int w = tid >> 5, lane = tid & 31;
    int c = (w & 1) * 32 + lane;
    int rg = (w >> 1) * 8;
    const float4* wv = (const float4*)(Wt + c * 68);

    for (int tile = blockIdx.x * 16; tile < N_NODES; tile += gridDim.x * 16) {
        __syncthreads();
        for (int i = tid; i < 16 * 16; i += 128) {
            int r = i >> 4, c4 = i & 15;
            size_t off = (size_t)(tile + r) * HF;
            float4 a = ((const float4*)(g_a + off))[c4];
            float4 sc = ((const float4*)s_sc)[c4];
            float4 sf = ((const float4*)s_sf)[c4];
            float4 v;
            v.x = fmaxf(a.x * sc.x + sf.x, 0.f);
            v.y = fmaxf(a.y * sc.y + sf.y, 0.f);
            v.z = fmaxf(a.z * sc.z + sf.z, 0.f);
            v.w = fmaxf(a.w * sc.w + sf.w, 0.f);
            xs[i] = v;
            ((float4*)(g_a + off))[c4] = v;   // x1 for the head
        }
        __syncthreads();
        unsigned long long al[8] = {0, 0, 0, 0, 0, 0, 0, 0};
        unsigned long long ah[8] = {0, 0, 0, 0, 0, 0, 0, 0};
#pragma unroll 4
        for (int k4 = 0; k4 < 16; k4++) {
            F4U wq; wq.f = wv[k4];
#pragma unroll
            for (int r = 0; r < 8; r++) {
                F4U xq; xq.f = xs[(rg + r) * 16 + k4];
                al[r] = ffma2(wq.u[0], xq.u[0], al[r]);
                ah[r] = ffma2(wq.u[1], xq.u[1], ah[r]);
            }
        }
#pragma unroll
        for (int r = 0; r < 8; r++) {
            float2 a = u2f(al[r]), b = u2f(ah[r]);
            g_h[(size_t)(tile + rg + r) * HF + c] = (a.x + a.y) + (b.x + b.y);
        }
    }
}

// ---------------- head: persistent; logits + log_softmax ----------------------
__global__ void k_final(const float* __restrict__ Wl, const float* __restrict__ bl,
                        float* __restrict__ out) {
    __shared__ __align__(16) float xs[32 * 132];    // concat features, pad 132
    __shared__ __align__(16) float Wlt[OUTF * 132]; // [j][k]
    __shared__ float ls[32 * 44];                   // logits
    __shared__ float bls[OUTF];

    int tid = threadIdx.x;
    for (int i = tid; i < IN_F * OUTF; i += 256) {
        int k = i / OUTF, j = i % OUTF;
        Wlt[j * 132 + k] = Wl[i];
    }
    if (tid < OUTF) bls[tid] = bl[tid];
    __syncthreads();

    int w = tid >> 5, r = tid & 31;
    int j0 = w * 5;
    int rr = tid >> 3, oo = tid & 7;

    for (int row0 = blockIdx.x * 32; row0 < N_NODES; row0 += gridDim.x * 32) {
        for (int i = tid; i < 32 * 32; i += 256) {
            int rw = i >> 5, c4 = i & 31;
            float4 v = (c4 < 16)
                ? ((const float4*)(g_a  + (size_t)(row0 + rw) * HF))[c4]
                : ((const float4*)(g_a2 + (size_t)(row0 + rw) * HF))[c4 - 16];
            ((float4*)(xs + rw * 132))[c4] = v;
        }
        __syncthreads();

        unsigned long long al[5] = {0, 0, 0, 0, 0};
        unsigned long long ah[5] = {0, 0, 0, 0, 0};
        const float4* xrv = (const float4*)(xs + r * 132);
#pragma unroll 4
        for (int k4 = 0; k4 < 32; k4++) {
            F4U xq; xq.f = xrv[k4];
#pragma unroll
            for (int cc = 0; cc < 5; cc++) {
                F4U wq; wq.f = ((const float4*)(Wlt + (j0 + cc) * 132))[k4];
                al[cc] = ffma2(xq.u[0], wq.u[0], al[cc]);
                ah[cc] = ffma2(xq.u[1], wq.u[1], ah[cc]);
            }
        }
#pragma unroll
        for (int cc = 0; cc < 5; cc++) {
            float2 a = u2f(al[cc]), b = u2f(ah[cc]);
            ls[r * 44 + j0 + cc] = (a.x + a.y) + (b.x + b.y) + bls[j0 + cc];
        }
        __syncthreads();

        const float* lr = ls + rr * 44 + oo * 5;
        float m = -INFINITY;
#pragma unroll
        for (int cc = 0; cc < 5; cc++) m = fmaxf(m, lr[cc]);
        for (int off = 4; off; off >>= 1) m = fmaxf(m, __shfl_xor_sync(0xffffffffu, m, off));
        float s = 0.f;
#pragma unroll
        for (int cc = 0; cc < 5; cc++) s += __expf(lr[cc] - m);
        for (int off = 4; off; off >>= 1) s += __shfl_xor_sync(0xffffffffu, s, off);
        float lse = m + __logf(s);
        float* op = out + (size_t)(row0 + rr) * OUTF + oo * 5;
#pragma unroll
        for (int cc = 0; cc < 5; cc++) op[cc] = lr[cc] - lse;
        __syncthreads();
    }
}

// ---------------- launch ------------------------------------------------------
extern "C" void kernel_launch(void* const* d_in, const int* in_sizes, int n_in,
                              void* d_out, int out_size) {
    const float* x0  = (const float*)d_in[0];
    const void*  ei  = d_in[1];
    const float* W1  = (const float*)d_in[2];
    const float* b1  = (const float*)d_in[3];
    const float* g1  = (const float*)d_in[4];
    const float* be1 = (const float*)d_in[5];
    const float* W2  = (const float*)d_in[6];
    const float* b2  = (const float*)d_in[7];
    const float* Wl  = (const float*)d_in[8];
    const float* bl  = (const float*)d_in[9];
    float* out = (float*)d_out;

    k_zero_detect<<<98, 1024>>>((const int*)ei);
    k_fatA<<<G1BLK + AUXBLK, 256>>>(x0, W1, ei);   // gemm1 (part 1) ∥ deg/cvt
    k_scanA<<<98, 1024>>>();
    k_scanB<<<1, 128>>>();
    k_scanC<<<98, 1024>>>();
    k_fatB<<<G1BLK + AUXBLK, 256>>>(x0, W1);       // gemm1 (part 2) ∥ bucket
    k_agg<<<12500, 256>>>(0, b1);
    k_gemm2<<<1480, 128>>>(W2, g1, be1);
    k_agg<<<12500, 256>>>(1, b2);
    k_final<<<592, 256>>>(Wl, bl, out);
}

// round 13
// speedup vs baseline: 1.1067x; 1.1067x over previous
#include <cuda_runtime.h>
#include <math.h>

#define N_NODES 100000
#define N_EDGES 1600000
#define IN_F    128
#define HF      64
#define OUTF    40
#define EPSB    1e-5f

// ---------------- f32x2 packed-FMA helpers ------------------------------------
union F4U { float4 f; unsigned long long u[2]; };

__device__ __forceinline__ unsigned long long ffma2(unsigned long long a,
                                                    unsigned long long b,
                                                    unsigned long long c) {
    unsigned long long d;
    asm("fma.rn.f32x2 %0, %1, %2, %3;" : "=l"(d) : "l"(a), "l"(b), "l"(c));
    return d;
}

__device__ __forceinline__ float2 u2f(unsigned long long v) {
    float2 f;
    asm("mov.b64 {%0, %1}, %2;" : "=f"(f.x), "=f"(f.y) : "l"(v));
    return f;
}

// ---------------- scratch (device globals; no allocation) ---------------------
__device__ __align__(16) float g_h  [N_NODES * HF];   // h1, then h2
__device__ __align__(16) float g_a  [N_NODES * HF];   // x1_pre -> x1
__device__ __align__(16) float g_a2 [N_NODES * HF];   // x2
__device__ float g_dinv[N_NODES];
__device__ int   g_deg [N_NODES];
__device__ int   g_rowloc[N_NODES];
__device__ int   g_rowstart[N_NODES + 1];
__device__ int   g_cursor[N_NODES];
__device__ int   g_btot[128];
__device__ int   g_boff[128];
__device__ int   g_src32[N_EDGES];
__device__ int   g_dst32[N_EDGES];
__device__ __align__(8) int2 g_edge[N_EDGES];        // {src, norm as float bits}
__device__ float g_sum [HF];
__device__ float g_sumsq[HF];
__device__ int   g_is64;

// ---------------- zero + dtype autodetect ------------------------------------
__global__ void k_zero_detect(const int* ei32) {
    int i = blockIdx.x * blockDim.x + threadIdx.x;
    if (i < N_NODES) g_deg[i] = 0;
    if (i < HF) { g_sum[i] = 0.f; g_sumsq[i] = 0.f; }
    if (i == 0) {
        int all0 = 1;
        for (int t = 0; t < 64; t++)
            if (ei32[2 * t + 1] != 0) { all0 = 0; break; }
        g_is64 = all0;
    }
}

// ---------------- degree count + int32 conversion -----------------------------
__global__ void k_deg_cvt(const void* ei) {
    int e = blockIdx.x * blockDim.x + threadIdx.x;
    if (e >= N_EDGES) return;
    int s, d;
    if (g_is64) {
        const long long* p = (const long long*)ei;
        s = (int)p[e];
        d = (int)p[N_EDGES + e];
    } else {
        const int* p = (const int*)ei;
        s = p[e];
        d = p[N_EDGES + e];
    }
    g_src32[e] = s;
    g_dst32[e] = d;
    atomicAdd(&g_deg[d], 1);
}

// ---------------- 3-phase exclusive scan over degrees --------------------------
__global__ void k_scanA() {
    __shared__ int sh[1024];
    int t = threadIdx.x;
    int i = blockIdx.x * 1024 + t;
    int v = (i < N_NODES) ? g_deg[i] : 0;
    sh[t] = v;
    __syncthreads();
    for (int off = 1; off < 1024; off <<= 1) {
        int x = (t >= off) ? sh[t - off] : 0;
        __syncthreads();
        sh[t] += x;
        __syncthreads();
    }
    if (i < N_NODES) g_rowloc[i] = sh[t] - v;
    if (t == 1023) g_btot[blockIdx.x] = sh[t];
}

__global__ void k_scanB() {
    __shared__ int sh[128];
    int t = threadIdx.x;
    int v = (t < 98) ? g_btot[t] : 0;
    sh[t] = v;
    __syncthreads();
    for (int off = 1; off < 128; off <<= 1) {
        int x = (t >= off) ? sh[t - off] : 0;
        __syncthreads();
        sh[t] += x;
        __syncthreads();
    }
    if (t < 98) g_boff[t] = sh[t] - v;
}

__global__ void k_scanC() {
    int i = blockIdx.x * blockDim.x + threadIdx.x;
    if (i < N_NODES) {
        int base = g_rowloc[i] + g_boff[i >> 10];
        g_rowstart[i] = base;
        g_cursor[i] = base;
        g_dinv[i] = rsqrtf((float)g_deg[i] + 1.0f);
    }
    if (i == 0) g_rowstart[N_NODES] = N_EDGES;
}

// ---------------- bucket fill: CSR by dst, single ST.64 payload ---------------
__global__ void k_bucket() {
    int e = blockIdx.x * blockDim.x + threadIdx.x;
    if (e >= N_EDGES) return;
    int s = g_src32[e];
    int d = g_dst32[e];
    int pos = atomicAdd(&g_cursor[d], 1);
    int2 pay;
    pay.x = s;
    pay.y = __float_as_int(g_dinv[s] * g_dinv[d]);
    g_edge[pos] = pay;
}

// ---------------- GEMM1: g_h = x0 @ W1 (100000x128 @ 128x64) -------------------
// 128 thr; 16-row tile; lane=col, acc 8 rows; f32x2 packed FMA.  (R4 exact)
__global__ void k_gemm1(const float* __restrict__ x0, const float* __restrict__ W1) {
    __shared__ __align__(16) float Wt[HF * 132];
    __shared__ __align__(16) float4 xs[16 * 32];   // [16 rows][128]

    int tid = threadIdx.x;
    for (int i = tid; i < IN_F * HF; i += 128) {
        int k = i >> 6, c = i & 63;
        Wt[c * 132 + k] = W1[i];
    }
    __syncthreads();

    int w = tid >> 5, lane = tid & 31;
    int c = (w & 1) * 32 + lane;
    int rg = (w >> 1) * 8;
    const float4* wv = (const float4*)(Wt + c * 132);

    for (int tile = blockIdx.x * 16; tile < N_NODES; tile += gridDim.x * 16) {
        __syncthreads();
        for (int i = tid; i < 16 * 32; i += 128) {
            int r = i >> 5, c4 = i & 31;
            xs[i] = ((const float4*)(x0 + (size_t)(tile + r) * IN_F))[c4];
        }
        __syncthreads();
        unsigned long long al[8] = {0, 0, 0, 0, 0, 0, 0, 0};
        unsigned long long ah[8] = {0, 0, 0, 0, 0, 0, 0, 0};
#pragma unroll 4
        for (int k4 = 0; k4 < 32; k4++) {
            F4U wq; wq.f = wv[k4];
#pragma unroll
            for (int r = 0; r < 8; r++) {
                F4U xq; xq.f = xs[(rg + r) * 32 + k4];
                al[r] = ffma2(wq.u[0], xq.u[0], al[r]);
                ah[r] = ffma2(wq.u[1], xq.u[1], ah[r]);
            }
        }
#pragma unroll
        for (int r = 0; r < 8; r++) {
            float2 a = u2f(al[r]), b = u2f(ah[r]);
            g_h[(size_t)(tile + rg + r) * HF + c] = (a.x + a.y) + (b.x + b.y);
        }
    }
}

// ---------------- aggregation: out[n] = sum_{e->n} h[src]*norm + h[n]*d2 + b ---
// warp per node; lane owns float2 of features.  (R4 exact, int2 edge load)
__global__ void k_agg(int layer, const float* __restrict__ bias) {
    const float* h = g_h;
    float* out = (layer == 0) ? g_a : g_a2;
    int n = blockIdx.x * 8 + (threadIdx.x >> 5);
    int lane = threadIdx.x & 31;
    int rs = g_rowstart[n];
    int re = g_rowstart[n + 1];
    float ax = 0.f, ay = 0.f;

    for (int j0 = rs; j0 < re; j0 += 32) {
        int idx = j0 + lane;
        int s = 0; float nrm = 0.f;
        if (idx < re) {
            int2 pay = g_edge[idx];
            s = pay.x;
            nrm = __int_as_float(pay.y);
        }
        int cnt = min(32, re - j0);
        int t = 0;
        for (; t + 4 <= cnt; t += 4) {
            int s0 = __shfl_sync(0xffffffffu, s, t);
            int s1 = __shfl_sync(0xffffffffu, s, t + 1);
            int s2 = __shfl_sync(0xffffffffu, s, t + 2);
            int s3 = __shfl_sync(0xffffffffu, s, t + 3);
            float n0 = __shfl_sync(0xffffffffu, nrm, t);
            float n1 = __shfl_sync(0xffffffffu, nrm, t + 1);
            float n2 = __shfl_sync(0xffffffffu, nrm, t + 2);
            float n3 = __shfl_sync(0xffffffffu, nrm, t + 3);
            float2 v0 = *(const float2*)(h + (size_t)s0 * HF + lane * 2);
            float2 v1 = *(const float2*)(h + (size_t)s1 * HF + lane * 2);
            float2 v2 = *(const float2*)(h + (size_t)s2 * HF + lane * 2);
            float2 v3 = *(const float2*)(h + (size_t)s3 * HF + lane * 2);
            ax = fmaf(v0.x, n0, ax); ay = fmaf(v0.y, n0, ay);
            ax = fmaf(v1.x, n1, ax); ay = fmaf(v1.y, n1, ay);
            ax = fmaf(v2.x, n2, ax); ay = fmaf(v2.y, n2, ay);
            ax = fmaf(v3.x, n3, ax); ay = fmaf(v3.y, n3, ay);
        }
        for (; t < cnt; t++) {
            int st = __shfl_sync(0xffffffffu, s, t);
            float nt = __shfl_sync(0xffffffffu, nrm, t);
            float2 v = *(const float2*)(h + (size_t)st * HF + lane * 2);
            ax = fmaf(v.x, nt, ax); ay = fmaf(v.y, nt, ay);
        }
    }
    float di = g_dinv[n];
    float d2 = di * di;
    float2 hv = *(const float2*)(h + (size_t)n * HF + lane * 2);
    float2 bv = *(const float2*)(bias + lane * 2);
    float2 o;
    o.x = ax + hv.x * d2 + bv.x;
    o.y = ay + hv.y * d2 + bv.y;
    *(float2*)(out + (size_t)n * HF + lane * 2) = o;
}

// ---------------- BN stats over g_a (R4 exact) ---------------------------------
__global__ void k_stats1() {
    int tid = blockIdx.x * blockDim.x + threadIdx.x;
    const int stride = 256 * 256;   // multiple of 64 -> fixed channel per thread
    float s = 0.f, s2 = 0.f;
    for (int i = tid; i < N_NODES * HF; i += stride) {
        float v = g_a[i];
        s += v;
        s2 += v * v;
    }
    __shared__ float sh0[256], sh1[256];
    sh0[threadIdx.x] = s;
    sh1[threadIdx.x] = s2;
    __syncthreads();
    if (threadIdx.x < 64) {
        float a = 0.f, b = 0.f;
        for (int j = threadIdx.x; j < 256; j += 64) { a += sh0[j]; b += sh1[j]; }
        atomicAdd(&g_sum[threadIdx.x], a);
        atomicAdd(&g_sumsq[threadIdx.x], b);
    }
}

// ---------------- GEMM2: BN+relu(g_a) -> x1 (to g_a); h2 = x1 @ W2 -> g_h ------
__global__ void k_gemm2(const float* __restrict__ W2,
                        const float* __restrict__ g1, const float* __restrict__ be1) {
    __shared__ __align__(16) float Wt[HF * 68];
    __shared__ __align__(16) float4 xs[16 * 16];   // [16 rows][64]
    __shared__ __align__(16) float s_sc[HF], s_sf[HF];

    int tid = threadIdx.x;
    for (int i = tid; i < HF * HF; i += 128) {
        int k = i >> 6, c = i & 63;
        Wt[c * 68 + k] = W2[i];
    }
    if (tid < HF) {
        float mu  = g_sum[tid] * (1.0f / N_NODES);
        float var = g_sumsq[tid] * (1.0f / N_NODES) - mu * mu;
        float sc  = rsqrtf(var + EPSB) * g1[tid];
        s_sc[tid] = sc;
        s_sf[tid] = be1[tid] - mu * sc;
    }
    __syncthreads();

    int w = tid >> 5, lane = tid & 31;
    int c = (w & 1) * 32 + lane;
    int rg = (w >> 1) * 8;
    const float4* wv = (const float4*)(Wt + c * 68);

    for (int tile = blockIdx.x * 16; tile < N_NODES; tile += gridDim.x * 16) {
        __syncthreads();
        for (int i = tid; i < 16 * 16; i += 128) {
            int r = i >> 4, c4 = i & 15;
            size_t off = (size_t)(tile + r) * HF;
            float4 a = ((const float4*)(g_a + off))[c4];
            float4 sc = ((const float4*)s_sc)[c4];
            float4 sf = ((const float4*)s_sf)[c4];
            float4 v;
            v.x = fmaxf(a.x * sc.x + sf.x, 0.f);
            v.y = fmaxf(a.y * sc.y + sf.y, 0.f);
            v.z = fmaxf(a.z * sc.z + sf.z, 0.f);
            v.w = fmaxf(a.w * sc.w + sf.w, 0.f);
            xs[i] = v;
            ((float4*)(g_a + off))[c4] = v;   // x1 for the head
        }
        __syncthreads();
        unsigned long long al[8] = {0, 0, 0, 0, 0, 0, 0, 0};
        unsigned long long ah[8] = {0, 0, 0, 0, 0, 0, 0, 0};
#pragma unroll 4
        for (int k4 = 0; k4 < 16; k4++) {
            F4U wq; wq.f = wv[k4];
#pragma unroll
            for (int r = 0; r < 8; r++) {
                F4U xq; xq.f = xs[(rg + r) * 16 + k4];
                al[r] = ffma2(wq.u[0], xq.u[0], al[r]);
                ah[r] = ffma2(wq.u[1], xq.u[1], ah[r]);
            }
        }
#pragma unroll
        for (int r = 0; r < 8; r++) {
            float2 a = u2f(al[r]), b = u2f(ah[r]);
            g_h[(size_t)(tile + rg + r) * HF + c] = (a.x + a.y) + (b.x + b.y);
        }
    }
}

// ---------------- head: logits = [x1|x2] @ Wl + bl; out = log_softmax ---------
// (R4 exact: non-persistent, 3125 blocks)
__global__ void k_final(const float* __restrict__ Wl, const float* __restrict__ bl,
                        float* __restrict__ out) {
    __shared__ __align__(16) float xs[32 * 132];    // concat features, pad 132
    __shared__ __align__(16) float Wlt[OUTF * 132]; // [j][k]
    __shared__ float ls[32 * 44];                   // logits
    __shared__ float bls[OUTF];

    int tid = threadIdx.x;
    for (int i = tid; i < IN_F * OUTF; i += 256) {
        int k = i / OUTF, j = i % OUTF;
        Wlt[j * 132 + k] = Wl[i];
    }
    if (tid < OUTF) bls[tid] = bl[tid];

    int row0 = blockIdx.x * 32;
    for (int i = tid; i < 32 * 32; i += 256) {
        int r = i >> 5, c4 = i & 31;
        float4 v = (c4 < 16)
            ? ((const float4*)(g_a  + (size_t)(row0 + r) * HF))[c4]
            : ((const float4*)(g_a2 + (size_t)(row0 + r) * HF))[c4 - 16];
        ((float4*)(xs + r * 132))[c4] = v;
    }
    __syncthreads();

    int w = tid >> 5, r = tid & 31;
    int j0 = w * 5;
    unsigned long long al[5] = {0, 0, 0, 0, 0};
    unsigned long long ah[5] = {0, 0, 0, 0, 0};
    const float4* xrv = (const float4*)(xs + r * 132);
#pragma unroll 4
    for (int k4 = 0; k4 < 32; k4++) {
        F4U xq; xq.f = xrv[k4];
#pragma unroll
        for (int cc = 0; cc < 5; cc++) {
            F4U wq; wq.f = ((const float4*)(Wlt + (j0 + cc) * 132))[k4];
            al[cc] = ffma2(xq.u[0], wq.u[0], al[cc]);
            ah[cc] = ffma2(xq.u[1], wq.u[1], ah[cc]);
        }
    }
#pragma unroll
    for (int cc = 0; cc < 5; cc++) {
        float2 a = u2f(al[cc]), b = u2f(ah[cc]);
        ls[r * 44 + j0 + cc] = (a.x + a.y) + (b.x + b.y) + bls[j0 + cc];
    }
    __syncthreads();

    // softmax: 8 threads per row (octets within warps), 5 cols each
    int rr = tid >> 3, oo = tid & 7;
    const float* lr = ls + rr * 44 + oo * 5;
    float m = -INFINITY;
#pragma unroll
    for (int cc = 0; cc < 5; cc++) m = fmaxf(m, lr[cc]);
    for (int off = 4; off; off >>= 1) m = fmaxf(m, __shfl_xor_sync(0xffffffffu, m, off));
    float s = 0.f;
#pragma unroll
    for (int cc = 0; cc < 5; cc++) s += __expf(lr[cc] - m);
    for (int off = 4; off; off >>= 1) s += __shfl_xor_sync(0xffffffffu, s, off);
    float lse = m + __logf(s);
    float* op = out + (size_t)(row0 + rr) * OUTF + oo * 5;
#pragma unroll
    for (int cc = 0; cc < 5; cc++) op[cc] = lr[cc] - lse;
}

// ---------------- launch ------------------------------------------------------
extern "C" void kernel_launch(void* const* d_in, const int* in_sizes, int n_in,
                              void* d_out, int out_size) {
    const float* x0  = (const float*)d_in[0];
    const void*  ei  = d_in[1];
    const float* W1  = (const float*)d_in[2];
    const float* b1  = (const float*)d_in[3];
    const float* g1  = (const float*)d_in[4];
    const float* be1 = (const float*)d_in[5];
    const float* W2  = (const float*)d_in[6];
    const float* b2  = (const float*)d_in[7];
    const float* Wl  = (const float*)d_in[8];
    const float* bl  = (const float*)d_in[9];
    float* out = (float*)d_out;

    k_zero_detect<<<98, 1024>>>((const int*)ei);
    k_deg_cvt<<<6250, 256>>>(ei);
    k_scanA<<<98, 1024>>>();
    k_scanB<<<1, 128>>>();
    k_scanC<<<98, 1024>>>();
    k_bucket<<<6250, 256>>>();
    k_gemm1<<<740, 128>>>(x0, W1);
    k_agg<<<12500, 256>>>(0, b1);
    k_stats1<<<256, 256>>>();
    k_gemm2<<<1480, 128>>>(W2, g1, be1);
    k_agg<<<12500, 256>>>(1, b2);
    k_final<<<3125, 256>>>(Wl, bl, out);
}